// round 2
// baseline (speedup 1.0000x reference)
#include <cuda_runtime.h>

#define NN 8192
#define KK 64
#define DD 256
#define HH 128

// ---- flat fp32 output layout (concat of reference tuple) ----
#define OFF_ADJ    0LL
#define OFF_FEAT   ((long long)NN * NN)
#define OFF_PROB   (OFF_FEAT + (long long)NN * DD)
#define OFF_PAIR   (OFF_PROB + (long long)NN * KK * 2)
#define OFF_BEFORE (OFF_PAIR + (long long)NN * KK * 2)
#define OFF_AFTER  (OFF_BEFORE + 1)
#define OFF_LEFT   (OFF_AFTER + 1)

// scratch: featW = feat @ W1   [N, 128]  (4 MB)
__device__ float g_featW[(size_t)NN * HH];

// ---------------------------------------------------------------------------
// Kernel 1: zero-fill new_adj (256 MB, issued FIRST so the DRAM write queue
// drains in the background) + featW = feat @ W1 (warp-per-row, 8 rows/block).
// Block lifetime ~= max(store drain, featw compute) -> fill is ~free compute-
// wise and featw is ~free bandwidth-wise.
// ---------------------------------------------------------------------------
__global__ void __launch_bounds__(256) fill_featw_kernel(const float* __restrict__ feat,
                                                         const float* __restrict__ W1,
                                                         float* __restrict__ out) {
    const int tid  = threadIdx.x;
    const int warp = tid >> 5;
    const int lane = tid & 31;

    // ---- zero-fill 8 adjacent adj rows (128 KB) : no dependencies, fire first
    float4* orow = reinterpret_cast<float4*>(out + (size_t)blockIdx.x * 8 * NN);
    const float4 z = make_float4(0.f, 0.f, 0.f, 0.f);
#pragma unroll
    for (int i = 0; i < 64; i++) orow[i * 256 + tid] = z;

    // ---- featW for 8 rows, one warp per row
    __shared__ float srow[8][DD];
    const int row = blockIdx.x * 8 + warp;
    const float4* f4 = reinterpret_cast<const float4*>(feat + (size_t)row * DD);
    float4* s4 = reinterpret_cast<float4*>(&srow[warp][0]);
    s4[lane]      = f4[lane];
    s4[lane + 32] = f4[lane + 32];
    __syncwarp();

    const float4* W14 = reinterpret_cast<const float4*>(W1);  // [256][32] float4
    float4 acc = make_float4(0.f, 0.f, 0.f, 0.f);
#pragma unroll 4
    for (int k = 0; k < DD; k++) {
        float s = srow[warp][k];
        float4 wv = W14[k * 32 + lane];
        acc.x = fmaf(s, wv.x, acc.x);
        acc.y = fmaf(s, wv.y, acc.y);
        acc.z = fmaf(s, wv.z, acc.z);
        acc.w = fmaf(s, wv.w, acc.w);
    }
    reinterpret_cast<float4*>(g_featW + (size_t)row * HH)[lane] = acc;

    if (blockIdx.x == 0 && tid == 0) {
        out[OFF_BEFORE] = 64.0f;   // E / dst == K
        out[OFF_AFTER]  = 0.0f;    // accumulated by edge_kernel atomics
    }
}

// ---------------------------------------------------------------------------
// Kernel 2: one block per dst row. adj already zeroed by kernel 1.
//   - prefetch adj gather + nbr at block start (latency hides under MLP)
//   - per-edge MLP head (warp per edge, 8 rounds), softmax -> prob/pair
//   - stable ascending rank (exact stable-argsort semantics)
//   - left_row, degree, after_edge_num, then scatter kept val/(deg+1e-6)
// ---------------------------------------------------------------------------
__global__ void __launch_bounds__(256) edge_kernel(const float* __restrict__ adj,
                                                   const int*   __restrict__ nbr,
                                                   const float* __restrict__ b1,
                                                   const float* __restrict__ prelu_a,
                                                   const float* __restrict__ W2,
                                                   const float* __restrict__ b2,
                                                   float* __restrict__ out) {
    __shared__ __align__(16) float sfw[HH];
    __shared__ float sp1[KK];
    __shared__ int   snbr[KK];
    __shared__ float sred[KK];
    __shared__ float scnt[KK];
    __shared__ float sdeg;

    const int row  = blockIdx.x;
    const int tid  = threadIdx.x;
    const int lane = tid & 31;
    const int warp = tid >> 5;

    // prefetch: neighbor list + adjacency values (consumed only after rank)
    float val_pref = 0.f;
    int   my_col   = 0;
    if (tid < KK) {
        my_col = nbr[row * KK + tid];
        snbr[tid] = my_col;
        val_pref = __ldg(adj + (size_t)row * NN + my_col);
    }
    if (tid < HH) sfw[tid] = g_featW[(size_t)row * HH + tid] + b1[tid];
    __syncthreads();

    // per-lane loop invariants (4 feature dims per lane)
    const float4 fs = reinterpret_cast<const float4*>(sfw)[lane];
    const int j0 = lane * 4;
    const float a0 = prelu_a[j0 + 0], a1 = prelu_a[j0 + 1],
                a2 = prelu_a[j0 + 2], a3 = prelu_a[j0 + 3];
    const float w00 = W2[(j0 + 0) * 2],     w01 = W2[(j0 + 0) * 2 + 1];
    const float w10 = W2[(j0 + 1) * 2],     w11 = W2[(j0 + 1) * 2 + 1];
    const float w20 = W2[(j0 + 2) * 2],     w21 = W2[(j0 + 2) * 2 + 1];
    const float w30 = W2[(j0 + 3) * 2],     w31 = W2[(j0 + 3) * 2 + 1];
    const float bb0 = b2[0], bb1 = b2[1];

    const float4* fW4 = reinterpret_cast<const float4*>(g_featW);

#pragma unroll
    for (int e = 0; e < 8; e++) {
        const int k   = e * 8 + warp;       // edge column within the row
        const int dst = snbr[k];
        float4 fd = fW4[(size_t)dst * 32 + lane];   // gathered 512B per warp
        float h0 = fs.x - fd.x, h1 = fs.y - fd.y;
        float h2 = fs.z - fd.z, h3 = fs.w - fd.w;
        h0 = (h0 >= 0.f) ? h0 : a0 * h0;
        h1 = (h1 >= 0.f) ? h1 : a1 * h1;
        h2 = (h2 >= 0.f) ? h2 : a2 * h2;
        h3 = (h3 >= 0.f) ? h3 : a3 * h3;
        float l0 = h0 * w00 + h1 * w10 + h2 * w20 + h3 * w30;
        float l1 = h0 * w01 + h1 * w11 + h2 * w21 + h3 * w31;
#pragma unroll
        for (int off = 16; off; off >>= 1) {
            l0 += __shfl_xor_sync(0xffffffffu, l0, off);
            l1 += __shfl_xor_sync(0xffffffffu, l1, off);
        }
        if (lane == 0) {
            l0 += bb0; l1 += bb1;
            float m  = fmaxf(l0, l1);
            float e0 = expf(l0 - m), e1 = expf(l1 - m);
            float inv = 1.0f / (e0 + e1);
            float p0 = e0 * inv, p1 = e1 * inv;
            long long eid = (long long)row * KK + k;
            reinterpret_cast<float2*>(out + OFF_PROB)[eid] = make_float2(p0, p1);
            reinterpret_cast<float2*>(out + OFF_PAIR)[eid] =
                make_float2((float)row, (float)dst);
            sp1[k] = p1;
        }
    }
    __syncthreads();

    // stable ascending rank (== stable argsort position)
    float val = 0.f;
    int   keep = 0;
    if (tid < KK) {
        const float mine = sp1[tid];
        int rank = 0;
#pragma unroll 8
        for (int j = 0; j < KK; j++) {
            float pj = sp1[j];
            rank += (pj < mine) || (pj == mine && j < tid);
        }
        if (rank >= 32) {                              // kept edge
            keep = 1;
            val = val_pref;
            out[OFF_LEFT + (long long)row * 32 + (rank - 32)] =
                (float)(row * KK + tid);
        }
        sred[tid] = val;
        scnt[tid] = (keep && val != 0.f) ? 1.f : 0.f;
    }
    __syncthreads();

    if (tid < 32) {
        float v = sred[tid] + sred[tid + 32];
        float c = scnt[tid] + scnt[tid + 32];
#pragma unroll
        for (int off = 16; off; off >>= 1) {
            v += __shfl_xor_sync(0xffffffffu, v, off);
            c += __shfl_xor_sync(0xffffffffu, c, off);
        }
        if (tid == 0) {
            sdeg = v;
            atomicAdd(out + OFF_AFTER, c * (1.0f / 8192.0f)); // exact multiples of 2^-8
        }
    }
    __syncthreads();   // publish sdeg

    if (keep) {
        out[(size_t)row * NN + my_col] = val / (sdeg + 1e-6f);
    }
}

// ---------------------------------------------------------------------------
extern "C" void kernel_launch(void* const* d_in, const int* in_sizes, int n_in,
                              void* d_out, int out_size) {
    const float* adj = nullptr; const float* feat = nullptr;
    const int*   nbr = nullptr; const float* W1   = nullptr;
    const float* b1  = nullptr; const float* pa   = nullptr;
    const float* W2  = nullptr; const float* b2   = nullptr;

    for (int i = 0; i < n_in; i++) {
        long long s = in_sizes[i];
        if      (s == (long long)NN * NN) adj  = (const float*)d_in[i];
        else if (s == (long long)NN * DD) feat = (const float*)d_in[i];
        else if (s == (long long)NN * KK) nbr  = (const int*)d_in[i];
        else if (s == (long long)DD * HH) W1   = (const float*)d_in[i];
        else if (s == HH) { if (!b1) b1 = (const float*)d_in[i];
                            else     pa = (const float*)d_in[i]; }
        else if (s == HH * 2) W2 = (const float*)d_in[i];
        else if (s == 2)      b2 = (const float*)d_in[i];
        // size-1 dst_num ignored (shapes are compile-time constants)
    }

    float* out = (float*)d_out;
    fill_featw_kernel<<<NN / 8, 256>>>(feat, W1, out);
    edge_kernel<<<NN, 256>>>(adj, nbr, b1, pa, W2, b2, out);
    cudaMemcpyAsync(out + OFF_FEAT, feat, (size_t)NN * DD * sizeof(float),
                    cudaMemcpyDeviceToDevice, 0);
}

// round 3
// speedup vs baseline: 1.2156x; 1.2156x over previous
#include <cuda_runtime.h>

#define NN 8192
#define KK 64
#define DD 256
#define HH 128
#define FILL_SPLIT 3072   // rows [0,FILL_SPLIT) zero-filled by kernel 1

// ---- flat fp32 output layout (concat of reference tuple) ----
#define OFF_ADJ    0LL
#define OFF_FEAT   ((long long)NN * NN)
#define OFF_PROB   (OFF_FEAT + (long long)NN * DD)
#define OFF_PAIR   (OFF_PROB + (long long)NN * KK * 2)
#define OFF_BEFORE (OFF_PAIR + (long long)NN * KK * 2)
#define OFF_AFTER  (OFF_BEFORE + 1)
#define OFF_LEFT   (OFF_AFTER + 1)

// scratch: featW = feat @ W1   [N, 128]  (4 MB, L2-resident for edge gather)
__device__ float g_featW[(size_t)NN * HH];

// ---------------------------------------------------------------------------
// Kernel 1: featW = feat @ W1 (warp-per-row, W1 staged through shared once per
// block) + feat copy to out (we already read it) + zero-fill of the first
// FILL_SPLIT adj rows (independent streaming stores hide under compute) +
// scalar outputs.
// ---------------------------------------------------------------------------
__global__ void __launch_bounds__(256) featw_kernel(const float* __restrict__ feat,
                                                    const float* __restrict__ W1,
                                                    float* __restrict__ out) {
    __shared__ __align__(16) float sW[32 * HH];   // one k-chunk of W1 (16 KB)
    __shared__ __align__(16) float srow[8][DD];   // 8 feat rows (8 KB)

    const int tid  = threadIdx.x;
    const int warp = tid >> 5;
    const int lane = tid & 31;
    const int row  = blockIdx.x * 8 + warp;

    // ---- streaming zero-fill of FILL_SPLIT/1024 rows per block (96 KB)
    {
        const float4 z = make_float4(0.f, 0.f, 0.f, 0.f);
        float4* dst = reinterpret_cast<float4*>(
            out + (size_t)blockIdx.x * (FILL_SPLIT / 1024) * NN);
#pragma unroll
        for (int i = 0; i < (FILL_SPLIT / 1024) * (NN / 4) / 256; i++)
            __stcs(&dst[i * 256 + tid], z);
    }

    // ---- load this warp's feat row into shared + copy to out (write-once)
    const float4* f4 = reinterpret_cast<const float4*>(feat + (size_t)row * DD);
    float4* s4 = reinterpret_cast<float4*>(&srow[warp][0]);
    float4 fa = f4[lane], fb = f4[lane + 32];
    s4[lane] = fa; s4[lane + 32] = fb;
    float4* oc = reinterpret_cast<float4*>(out + OFF_FEAT + (size_t)row * DD);
    __stcs(&oc[lane], fa); __stcs(&oc[lane + 32], fb);

    const float4* W14 = reinterpret_cast<const float4*>(W1); // [256][32] float4
    const float4* sW4 = reinterpret_cast<const float4*>(sW);
    float4 acc = make_float4(0.f, 0.f, 0.f, 0.f);

#pragma unroll 1
    for (int c = 0; c < 8; c++) {                 // 8 k-chunks of 32
        __syncthreads();
        // stage W1 chunk: 1024 float4, 4 per thread, coalesced
        float4* sWst = reinterpret_cast<float4*>(sW);
#pragma unroll
        for (int i = 0; i < 4; i++)
            sWst[i * 256 + tid] = W14[c * 1024 + i * 256 + tid];
        __syncthreads();
#pragma unroll
        for (int kk = 0; kk < 32; kk++) {
            float s = srow[warp][c * 32 + kk];
            float4 wv = sW4[kk * 32 + lane];
            acc.x = fmaf(s, wv.x, acc.x);
            acc.y = fmaf(s, wv.y, acc.y);
            acc.z = fmaf(s, wv.z, acc.z);
            acc.w = fmaf(s, wv.w, acc.w);
        }
    }
    reinterpret_cast<float4*>(g_featW + (size_t)row * HH)[lane] = acc;

    if (blockIdx.x == 0 && tid == 0) {
        out[OFF_BEFORE] = 64.0f;
        out[OFF_AFTER]  = 0.0f;
    }
}

// ---------------------------------------------------------------------------
// Kernel 2: one block per dst row.
//   - zero-fill own row early (rows >= FILL_SPLIT), streaming stores
//   - pair_list stored off the critical path
//   - 8-deep prefetch of featW gathers per warp, then 8 independent edge MLPs
//     and 8 interleaved butterfly reductions (kills the MLP=1 stall chain)
//   - softmax on 64 coalesced threads; stable rank; left_row; degree; scatter
// ---------------------------------------------------------------------------
__global__ void __launch_bounds__(256) edge_kernel(const float* __restrict__ adj,
                                                   const int*   __restrict__ nbr,
                                                   const float* __restrict__ b1,
                                                   const float* __restrict__ prelu_a,
                                                   const float* __restrict__ W2,
                                                   const float* __restrict__ b2,
                                                   float* __restrict__ out) {
    __shared__ __align__(16) float sfw[HH];
    __shared__ float sl0[KK], sl1[KK], sp1[KK];
    __shared__ int   snbr[KK];
    __shared__ float sred[KK], scnt[KK];
    __shared__ float sdeg;

    const int row  = blockIdx.x;
    const int tid  = threadIdx.x;
    const int lane = tid & 31;
    const int warp = tid >> 5;

    // small loads first (they gate the first sync)
    float val_pref = 0.f;
    int   my_col   = 0;
    if (tid < KK) {
        my_col = nbr[row * KK + tid];
        snbr[tid] = my_col;
        val_pref = __ldg(adj + (size_t)row * NN + my_col);
    }
    if (tid < HH) sfw[tid] = g_featW[(size_t)row * HH + tid] + b1[tid];

    // streaming zero-fill of this row (independent; drains during compute)
    if (row >= FILL_SPLIT) {
        float4* orow = reinterpret_cast<float4*>(out + (size_t)row * NN);
        const float4 z = make_float4(0.f, 0.f, 0.f, 0.f);
#pragma unroll
        for (int i = 0; i < 8; i++) __stcs(&orow[i * 256 + tid], z);
    }
    __syncthreads();

    // pair_list: independent of MLP
    if (tid < KK)
        __stcs(&reinterpret_cast<float2*>(out + OFF_PAIR)[(long long)row * KK + tid],
               make_float2((float)row, (float)snbr[tid]));

    // per-lane invariants
    const float4 fs = reinterpret_cast<const float4*>(sfw)[lane];
    const int j0 = lane * 4;
    const float a0 = prelu_a[j0 + 0], a1 = prelu_a[j0 + 1],
                a2 = prelu_a[j0 + 2], a3 = prelu_a[j0 + 3];
    const float w00 = W2[(j0 + 0) * 2], w01 = W2[(j0 + 0) * 2 + 1];
    const float w10 = W2[(j0 + 1) * 2], w11 = W2[(j0 + 1) * 2 + 1];
    const float w20 = W2[(j0 + 2) * 2], w21 = W2[(j0 + 2) * 2 + 1];
    const float w30 = W2[(j0 + 3) * 2], w31 = W2[(j0 + 3) * 2 + 1];

    const float4* fW4 = reinterpret_cast<const float4*>(g_featW);

    // 8-deep gather prefetch (this warp's 8 edges: k = e*8 + warp)
    float4 fd[8];
#pragma unroll
    for (int e = 0; e < 8; e++)
        fd[e] = fW4[(size_t)snbr[e * 8 + warp] * 32 + lane];

    float l0[8], l1[8];
#pragma unroll
    for (int e = 0; e < 8; e++) {
        float h0 = fs.x - fd[e].x, h1 = fs.y - fd[e].y;
        float h2 = fs.z - fd[e].z, h3 = fs.w - fd[e].w;
        h0 = (h0 >= 0.f) ? h0 : a0 * h0;
        h1 = (h1 >= 0.f) ? h1 : a1 * h1;
        h2 = (h2 >= 0.f) ? h2 : a2 * h2;
        h3 = (h3 >= 0.f) ? h3 : a3 * h3;
        l0[e] = h0 * w00 + h1 * w10 + h2 * w20 + h3 * w30;
        l1[e] = h0 * w01 + h1 * w11 + h2 * w21 + h3 * w31;
    }
    // 8 independent butterfly reductions (pipelined, no serial dependence)
#pragma unroll
    for (int off = 16; off; off >>= 1) {
#pragma unroll
        for (int e = 0; e < 8; e++) {
            l0[e] += __shfl_xor_sync(0xffffffffu, l0[e], off);
            l1[e] += __shfl_xor_sync(0xffffffffu, l1[e], off);
        }
    }
    if (lane == 0) {
#pragma unroll
        for (int e = 0; e < 8; e++) {
            sl0[e * 8 + warp] = l0[e];
            sl1[e * 8 + warp] = l1[e];
        }
    }
    __syncthreads();

    // softmax on 64 coalesced threads (same math order as validated R1)
    if (tid < KK) {
        float L0 = sl0[tid] + b2[0];
        float L1 = sl1[tid] + b2[1];
        float m  = fmaxf(L0, L1);
        float e0 = expf(L0 - m), e1 = expf(L1 - m);
        float inv = 1.0f / (e0 + e1);
        float p0 = e0 * inv, p1 = e1 * inv;
        __stcs(&reinterpret_cast<float2*>(out + OFF_PROB)[(long long)row * KK + tid],
               make_float2(p0, p1));
        sp1[tid] = p1;
    }
    __syncthreads();

    // stable ascending rank (exact stable-argsort semantics)
    float val = 0.f;
    int   keep = 0;
    if (tid < KK) {
        const float mine = sp1[tid];
        int rank = 0;
#pragma unroll 8
        for (int j = 0; j < KK; j++) {
            float pj = sp1[j];
            rank += (pj < mine) || (pj == mine && j < tid);
        }
        if (rank >= 32) {
            keep = 1;
            val = val_pref;
            __stcs(&out[OFF_LEFT + (long long)row * 32 + (rank - 32)],
                   (float)(row * KK + tid));
        }
        sred[tid] = val;
        scnt[tid] = (keep && val != 0.f) ? 1.f : 0.f;
    }
    __syncthreads();

    if (tid < 32) {
        float v = sred[tid] + sred[tid + 32];
        float c = scnt[tid] + scnt[tid + 32];
#pragma unroll
        for (int off = 16; off; off >>= 1) {
            v += __shfl_xor_sync(0xffffffffu, v, off);
            c += __shfl_xor_sync(0xffffffffu, c, off);
        }
        if (tid == 0) {
            sdeg = v;
            atomicAdd(out + OFF_AFTER, c * (1.0f / 8192.0f));
        }
    }
    __syncthreads();   // publish sdeg; order fill before scatter

    if (keep) {
        __stcs(&out[(size_t)row * NN + my_col], val / (sdeg + 1e-6f));
    }
}

// ---------------------------------------------------------------------------
extern "C" void kernel_launch(void* const* d_in, const int* in_sizes, int n_in,
                              void* d_out, int out_size) {
    const float* adj = nullptr; const float* feat = nullptr;
    const int*   nbr = nullptr; const float* W1   = nullptr;
    const float* b1  = nullptr; const float* pa   = nullptr;
    const float* W2  = nullptr; const float* b2   = nullptr;

    for (int i = 0; i < n_in; i++) {
        long long s = in_sizes[i];
        if      (s == (long long)NN * NN) adj  = (const float*)d_in[i];
        else if (s == (long long)NN * DD) feat = (const float*)d_in[i];
        else if (s == (long long)NN * KK) nbr  = (const int*)d_in[i];
        else if (s == (long long)DD * HH) W1   = (const float*)d_in[i];
        else if (s == HH) { if (!b1) b1 = (const float*)d_in[i];
                            else     pa = (const float*)d_in[i]; }
        else if (s == HH * 2) W2 = (const float*)d_in[i];
        else if (s == 2)      b2 = (const float*)d_in[i];
    }

    float* out = (float*)d_out;
    featw_kernel<<<NN / 8, 256>>>(feat, W1, out);
    edge_kernel<<<NN, 256>>>(adj, nbr, b1, pa, W2, b2, out);
}

// round 4
// speedup vs baseline: 1.4642x; 1.2045x over previous
#include <cuda_runtime.h>

#define NN 8192
#define KK 64
#define DD 256
#define HH 128
#define K1_BLOCKS   128
#define K1_THREADS  512
#define K1_FILLROWS 2048          // adj rows zero-filled by kernel 1 (64 MB)

// ---- flat fp32 output layout (concat of reference tuple) ----
#define OFF_ADJ    0LL
#define OFF_FEAT   ((long long)NN * NN)
#define OFF_PROB   (OFF_FEAT + (long long)NN * DD)
#define OFF_PAIR   (OFF_PROB + (long long)NN * KK * 2)
#define OFF_BEFORE (OFF_PAIR + (long long)NN * KK * 2)
#define OFF_AFTER  (OFF_BEFORE + 1)
#define OFF_LEFT   (OFF_AFTER + 1)

// scratch: featW = feat @ W1   [N, 128]  (4 MB, L2-resident for edge gather)
__device__ float g_featW[(size_t)NN * HH];

// ---------------------------------------------------------------------------
// Kernel 1: featW = feat @ W1.
//  - full W1 (128 KB) staged into dynamic smem ONCE per block (no chunk syncs)
//  - 512 threads, 64 rows/block (16 warps x 4 rows, 2 rows per inner pass)
//  - fused: feat copy to out, 16 adj rows zero-fill per block (DRAM-idle here)
// ---------------------------------------------------------------------------
extern __shared__ float k1_smem[];

__global__ void __launch_bounds__(K1_THREADS) featw_kernel(const float* __restrict__ feat,
                                                           const float* __restrict__ W1,
                                                           float* __restrict__ out) {
    float* sW   = k1_smem;                 // 256*128 floats = 128 KB
    float* srow = k1_smem + DD * HH;       // 16 warps * 2 rows * 256 = 32 KB

    const int tid  = threadIdx.x;
    const int warp = tid >> 5;
    const int lane = tid & 31;

    // ---- zero-fill 16 adj rows (512 KB) with streaming stores (fire first)
    {
        const float4 z = make_float4(0.f, 0.f, 0.f, 0.f);
        float4* dst = reinterpret_cast<float4*>(out + (size_t)blockIdx.x * 16 * NN);
#pragma unroll
        for (int i = 0; i < 64; i++) __stcs(&dst[i * K1_THREADS + tid], z);
    }

    // ---- stage full W1: 8192 float4, 16 per thread, coalesced
    {
        const float4* W14 = reinterpret_cast<const float4*>(W1);
        float4* sW4 = reinterpret_cast<float4*>(sW);
#pragma unroll
        for (int i = 0; i < 16; i++) sW4[i * K1_THREADS + tid] = W14[i * K1_THREADS + tid];
    }
    __syncthreads();

    const float4* sW4 = reinterpret_cast<const float4*>(sW);
    float* rowA = srow + warp * 2 * DD;
    float* rowB = rowA + DD;

#pragma unroll 1
    for (int rp = 0; rp < 2; rp++) {
        const int row0 = blockIdx.x * 64 + warp * 4 + rp * 2;
        const int row1 = row0 + 1;

        // load 2 feat rows -> shared (+ streaming copy to out)
        const float4* fA = reinterpret_cast<const float4*>(feat + (size_t)row0 * DD);
        const float4* fB = reinterpret_cast<const float4*>(feat + (size_t)row1 * DD);
        float4 a0 = fA[lane], a1 = fA[lane + 32];
        float4 b0 = fB[lane], b1v = fB[lane + 32];
        reinterpret_cast<float4*>(rowA)[lane]      = a0;
        reinterpret_cast<float4*>(rowA)[lane + 32] = a1;
        reinterpret_cast<float4*>(rowB)[lane]      = b0;
        reinterpret_cast<float4*>(rowB)[lane + 32] = b1v;
        float4* ocA = reinterpret_cast<float4*>(out + OFF_FEAT + (size_t)row0 * DD);
        float4* ocB = reinterpret_cast<float4*>(out + OFF_FEAT + (size_t)row1 * DD);
        __stcs(&ocA[lane], a0); __stcs(&ocA[lane + 32], a1);
        __stcs(&ocB[lane], b0); __stcs(&ocB[lane + 32], b1v);
        __syncwarp();

        float4 accA = make_float4(0.f, 0.f, 0.f, 0.f);
        float4 accB = make_float4(0.f, 0.f, 0.f, 0.f);
#pragma unroll 8
        for (int k = 0; k < DD; k++) {
            float4 wv = sW4[k * 32 + lane];
            float sA = rowA[k], sB = rowB[k];
            accA.x = fmaf(sA, wv.x, accA.x); accA.y = fmaf(sA, wv.y, accA.y);
            accA.z = fmaf(sA, wv.z, accA.z); accA.w = fmaf(sA, wv.w, accA.w);
            accB.x = fmaf(sB, wv.x, accB.x); accB.y = fmaf(sB, wv.y, accB.y);
            accB.z = fmaf(sB, wv.z, accB.z); accB.w = fmaf(sB, wv.w, accB.w);
        }
        reinterpret_cast<float4*>(g_featW + (size_t)row0 * HH)[lane] = accA;
        reinterpret_cast<float4*>(g_featW + (size_t)row1 * HH)[lane] = accB;
        __syncwarp();
    }

    if (blockIdx.x == 0 && tid == 0) {
        out[OFF_BEFORE] = 64.0f;
        out[OFF_AFTER]  = 0.0f;
    }
}

// ---------------------------------------------------------------------------
// Kernel 2: one block per dst row.
//  - D = L1 - L0 only (monotone for ranking; sigmoid -> p0,p1): halves the
//    butterfly (5 shuffles/edge) and the GEMV (wd = w2[:,1]-w2[:,0])
//  - gathers in 2 batches of 4 (regs ~45, 5 blocks/SM)
//  - zero-fill own row (rows >= K1_FILLROWS) with streaming stores, early
// ---------------------------------------------------------------------------
__global__ void __launch_bounds__(256, 5) edge_kernel(const float* __restrict__ adj,
                                                      const int*   __restrict__ nbr,
                                                      const float* __restrict__ b1,
                                                      const float* __restrict__ prelu_a,
                                                      const float* __restrict__ W2,
                                                      const float* __restrict__ b2,
                                                      float* __restrict__ out) {
    __shared__ __align__(16) float sfw[HH];
    __shared__ float sD[KK], sp1[KK];
    __shared__ int   snbr[KK];
    __shared__ float sred[KK], scnt[KK];
    __shared__ float sdeg;

    const int row  = blockIdx.x;
    const int tid  = threadIdx.x;
    const int lane = tid & 31;
    const int warp = tid >> 5;

    float val_pref = 0.f;
    int   my_col   = 0;
    if (tid < KK) {
        my_col = nbr[row * KK + tid];
        snbr[tid] = my_col;
        val_pref = __ldg(adj + (size_t)row * NN + my_col);
    }
    if (tid < HH) sfw[tid] = g_featW[(size_t)row * HH + tid] + b1[tid];

    if (row >= K1_FILLROWS) {                       // streaming zero-fill (32 KB)
        float4* orow = reinterpret_cast<float4*>(out + (size_t)row * NN);
        const float4 z = make_float4(0.f, 0.f, 0.f, 0.f);
#pragma unroll
        for (int i = 0; i < 8; i++) __stcs(&orow[i * 256 + tid], z);
    }
    __syncthreads();

    if (tid < KK)                                    // pair_list (off critical path)
        __stcs(&reinterpret_cast<float2*>(out + OFF_PAIR)[(long long)row * KK + tid],
               make_float2((float)row, (float)snbr[tid]));

    const float4 fs = reinterpret_cast<const float4*>(sfw)[lane];
    const int j0 = lane * 4;
    const float a0 = prelu_a[j0 + 0], a1 = prelu_a[j0 + 1],
                a2 = prelu_a[j0 + 2], a3 = prelu_a[j0 + 3];
    const float wd0 = W2[(j0 + 0) * 2 + 1] - W2[(j0 + 0) * 2];
    const float wd1 = W2[(j0 + 1) * 2 + 1] - W2[(j0 + 1) * 2];
    const float wd2 = W2[(j0 + 2) * 2 + 1] - W2[(j0 + 2) * 2];
    const float wd3 = W2[(j0 + 3) * 2 + 1] - W2[(j0 + 3) * 2];

    const float4* fW4 = reinterpret_cast<const float4*>(g_featW);
    float dd[8];

#pragma unroll
    for (int b = 0; b < 2; b++) {                   // 2 gather batches of 4
        float4 fd[4];
#pragma unroll
        for (int e = 0; e < 4; e++)
            fd[e] = fW4[(size_t)snbr[(b * 4 + e) * 8 + warp] * 32 + lane];
#pragma unroll
        for (int e = 0; e < 4; e++) {
            float h0 = fs.x - fd[e].x, h1 = fs.y - fd[e].y;
            float h2 = fs.z - fd[e].z, h3 = fs.w - fd[e].w;
            h0 = (h0 >= 0.f) ? h0 : a0 * h0;
            h1 = (h1 >= 0.f) ? h1 : a1 * h1;
            h2 = (h2 >= 0.f) ? h2 : a2 * h2;
            h3 = (h3 >= 0.f) ? h3 : a3 * h3;
            dd[b * 4 + e] = h0 * wd0 + h1 * wd1 + h2 * wd2 + h3 * wd3;
        }
    }
#pragma unroll
    for (int off = 16; off; off >>= 1) {            // 8 independent butterflies
#pragma unroll
        for (int e = 0; e < 8; e++)
            dd[e] += __shfl_xor_sync(0xffffffffu, dd[e], off);
    }
    if (lane == 0) {
#pragma unroll
        for (int e = 0; e < 8; e++) sD[e * 8 + warp] = dd[e];
    }
    __syncthreads();

    // sigmoid probs (== softmax of (L0,L1) to ~1 ulp); D includes b2 diff
    if (tid < KK) {
        float D  = sD[tid] + (b2[1] - b2[0]);
        float p1 = 1.0f / (1.0f + expf(-D));
        float p0 = 1.0f / (1.0f + expf(D));
        __stcs(&reinterpret_cast<float2*>(out + OFF_PROB)[(long long)row * KK + tid],
               make_float2(p0, p1));
        sp1[tid] = p1;
    }
    __syncthreads();

    // stable ascending rank on p1 (exact stable-argsort semantics)
    float val = 0.f;
    int   keep = 0;
    if (tid < KK) {
        const float mine = sp1[tid];
        int rank = 0;
#pragma unroll 8
        for (int j = 0; j < KK; j++) {
            float pj = sp1[j];
            rank += (pj < mine) || (pj == mine && j < tid);
        }
        if (rank >= 32) {
            keep = 1;
            val = val_pref;
            __stcs(&out[OFF_LEFT + (long long)row * 32 + (rank - 32)],
                   (float)(row * KK + tid));
        }
        sred[tid] = val;
        scnt[tid] = (keep && val != 0.f) ? 1.f : 0.f;
    }
    __syncthreads();

    if (tid < 32) {
        float v = sred[tid] + sred[tid + 32];
        float c = scnt[tid] + scnt[tid + 32];
#pragma unroll
        for (int off = 16; off; off >>= 1) {
            v += __shfl_xor_sync(0xffffffffu, v, off);
            c += __shfl_xor_sync(0xffffffffu, c, off);
        }
        if (tid == 0) {
            sdeg = v;
            atomicAdd(out + OFF_AFTER, c * (1.0f / 8192.0f));
        }
    }
    __syncthreads();

    if (keep) {
        __stcs(&out[(size_t)row * NN + my_col], val / (sdeg + 1e-6f));
    }
}

// ---------------------------------------------------------------------------
extern "C" void kernel_launch(void* const* d_in, const int* in_sizes, int n_in,
                              void* d_out, int out_size) {
    const float* adj = nullptr; const float* feat = nullptr;
    const int*   nbr = nullptr; const float* W1   = nullptr;
    const float* b1  = nullptr; const float* pa   = nullptr;
    const float* W2  = nullptr; const float* b2   = nullptr;

    for (int i = 0; i < n_in; i++) {
        long long s = in_sizes[i];
        if      (s == (long long)NN * NN) adj  = (const float*)d_in[i];
        else if (s == (long long)NN * DD) feat = (const float*)d_in[i];
        else if (s == (long long)NN * KK) nbr  = (const int*)d_in[i];
        else if (s == (long long)DD * HH) W1   = (const float*)d_in[i];
        else if (s == HH) { if (!b1) b1 = (const float*)d_in[i];
                            else     pa = (const float*)d_in[i]; }
        else if (s == HH * 2) W2 = (const float*)d_in[i];
        else if (s == 2)      b2 = (const float*)d_in[i];
    }

    float* out = (float*)d_out;
    const int k1_smem_bytes = (DD * HH + 16 * 2 * DD) * (int)sizeof(float); // 160 KB
    static int attr_done = 0;
    if (!attr_done) {
        cudaFuncSetAttribute(featw_kernel,
                             cudaFuncAttributeMaxDynamicSharedMemorySize, k1_smem_bytes);
        attr_done = 1;
    }
    featw_kernel<<<K1_BLOCKS, K1_THREADS, k1_smem_bytes>>>(feat, W1, out);
    edge_kernel<<<NN, 256>>>(adj, nbr, b1, pa, W2, b2, out);
}